// round 4
// baseline (speedup 1.0000x reference)
#include <cuda_runtime.h>
#include <cuda_bf16.h>

#define MAX_NODES 2097152
__device__ float4 g_pred4[MAX_NODES];   // pre-scaled nodal displacements (x*uc, y*uc, th*tc, 0)
__device__ float4 g_Fint4[MAX_NODES];   // accumulated internal forces (w unused)
__device__ double g_sumR;
__device__ double g_sumF;
__device__ unsigned int g_ticket;

// Pass 1: pack+scale pred into float4 AND zero the accumulator. 4 nodes/thread.
__global__ void pack_kernel(const float4* __restrict__ pred4in,
                            const float* __restrict__ pred,
                            const float* __restrict__ u_c,
                            const float* __restrict__ th_c,
                            int Ngrp, int N) {
    const float uc = __ldg(u_c);
    const float tc = __ldg(th_c);
    const float4 z = make_float4(0.f, 0.f, 0.f, 0.f);
    int g = blockIdx.x * blockDim.x + threadIdx.x;
    const int stride = gridDim.x * blockDim.x;
    for (; g < Ngrp; g += stride) {
        const float4 p0 = pred4in[3 * g + 0];
        const float4 p1 = pred4in[3 * g + 1];
        const float4 p2 = pred4in[3 * g + 2];
        const int n = 4 * g;
        g_pred4[n + 0] = make_float4(p0.x * uc, p0.y * uc, p0.z * tc, 0.f);
        g_pred4[n + 1] = make_float4(p0.w * uc, p1.x * uc, p1.y * tc, 0.f);
        g_pred4[n + 2] = make_float4(p1.z * uc, p1.w * uc, p2.x * tc, 0.f);
        g_pred4[n + 3] = make_float4(p2.y * uc, p2.z * uc, p2.w * tc, 0.f);
        g_Fint4[n + 0] = z;
        g_Fint4[n + 1] = z;
        g_Fint4[n + 2] = z;
        g_Fint4[n + 3] = z;
    }
    // scalar tail
    int i = 4 * Ngrp + (blockIdx.x * blockDim.x + threadIdx.x);
    if (i < N) {
        g_pred4[i] = make_float4(pred[3 * i] * uc, pred[3 * i + 1] * uc,
                                 pred[3 * i + 2] * tc, 0.f);
        g_Fint4[i] = z;
    }
}

__device__ __forceinline__ void red_v4(float4* addr, float x, float y, float z, float w) {
    asm volatile("red.global.add.v4.f32 [%0], {%1, %2, %3, %4};"
                 :: "l"(addr), "f"(x), "f"(y), "f"(z), "f"(w) : "memory");
}

// Pass 2: per-element local forces, 2 elements/thread, scatter-add via v4 REDG.
__global__ void __launch_bounds__(256) elem_kernel(
        const float2* __restrict__ L2,
        const float2* __restrict__ pE2,
        const float2* __restrict__ pA2,
        const float2* __restrict__ pI2,
        const float2* __restrict__ dirs2,
        const int4*   __restrict__ conn4,
        int Egrp) {
    const int t = blockIdx.x * blockDim.x + threadIdx.x;
    if (t >= Egrp) return;

    // Front-batched streaming loads for both elements.
    const int4   ab  = conn4[t];           // (nA0, nB0, nA1, nB1)
    const float2 Lv  = L2[t];
    const float2 Ev  = pE2[t];
    const float2 Av  = pA2[t];
    const float2 Iv  = pI2[t];
    const float2 d0  = dirs2[3 * t + 0];   // (c0, 0)
    const float2 d1  = dirs2[3 * t + 1];   // (s0, c1)
    const float2 d2  = dirs2[3 * t + 2];   // (0, s1)

    // Gathers (4 independent — high MLP)
    const float4 a0 = g_pred4[ab.x];
    const float4 b0 = g_pred4[ab.y];
    const float4 a1 = g_pred4[ab.z];
    const float4 b1 = g_pred4[ab.w];

    // element 0
    {
        const float c = d0.x, s = d1.x;
        const float inv_L = 1.0f / Lv.x;
        const float EA = Ev.x * Av.x;
        const float EI = Ev.x * Iv.x;
        const float u_A  =  c * a0.x + s * a0.y;
        const float w_A  = -s * a0.x + c * a0.y;
        const float thA  = -a0.z;
        const float u_B  =  c * b0.x + s * b0.y;
        const float w_B  = -s * b0.x + c * b0.y;
        const float thB  = -b0.z;
        const float ea_l  = EA * inv_L;
        const float ei_l  = EI * inv_L;
        const float ei_l2 = ei_l * inv_L;
        const float ei_l3 = ei_l2 * inv_L;
        const float dw = w_A - w_B;
        const float f0 = ea_l * (u_A - u_B);
        const float f1 = 12.0f * ei_l3 * dw + 6.0f * ei_l2 * (thA + thB);
        const float f2 = 6.0f * ei_l2 * dw + 4.0f * ei_l * thA + 2.0f * ei_l * thB;
        const float f5 = 6.0f * ei_l2 * dw + 2.0f * ei_l * thA + 4.0f * ei_l * thB;
        const float fAx = c * f0 - s * f1;
        const float fAy = s * f0 + c * f1;
        red_v4(&g_Fint4[ab.x],  fAx,  fAy, -f2, 0.0f);
        red_v4(&g_Fint4[ab.y], -fAx, -fAy, -f5, 0.0f);
    }
    // element 1
    {
        const float c = d1.y, s = d2.y;
        const float inv_L = 1.0f / Lv.y;
        const float EA = Ev.y * Av.y;
        const float EI = Ev.y * Iv.y;
        const float u_A  =  c * a1.x + s * a1.y;
        const float w_A  = -s * a1.x + c * a1.y;
        const float thA  = -a1.z;
        const float u_B  =  c * b1.x + s * b1.y;
        const float w_B  = -s * b1.x + c * b1.y;
        const float thB  = -b1.z;
        const float ea_l  = EA * inv_L;
        const float ei_l  = EI * inv_L;
        const float ei_l2 = ei_l * inv_L;
        const float ei_l3 = ei_l2 * inv_L;
        const float dw = w_A - w_B;
        const float f0 = ea_l * (u_A - u_B);
        const float f1 = 12.0f * ei_l3 * dw + 6.0f * ei_l2 * (thA + thB);
        const float f2 = 6.0f * ei_l2 * dw + 4.0f * ei_l * thA + 2.0f * ei_l * thB;
        const float f5 = 6.0f * ei_l2 * dw + 2.0f * ei_l * thA + 4.0f * ei_l * thB;
        const float fAx = c * f0 - s * f1;
        const float fAy = s * f0 + c * f1;
        red_v4(&g_Fint4[ab.z],  fAx,  fAy, -f2, 0.0f);
        red_v4(&g_Fint4[ab.w], -fAx, -fAy, -f5, 0.0f);
    }
}

// Scalar-tail elem kernel for odd E (launched only if needed).
__global__ void elem_tail_kernel(const float* __restrict__ L,
                                 const float* __restrict__ pE,
                                 const float* __restrict__ pA,
                                 const float* __restrict__ pI,
                                 const float* __restrict__ dirs,
                                 const int2*  __restrict__ conn,
                                 int start, int E) {
    int e = start + blockIdx.x * blockDim.x + threadIdx.x;
    if (e >= E) return;
    const int2 ab = conn[e];
    const float c = dirs[3 * e + 0];
    const float s = dirs[3 * e + 2];
    const float inv_L = 1.0f / L[e];
    const float Ee = pE[e];
    const float EA = Ee * pA[e];
    const float EI = Ee * pI[e];
    const float4 a = g_pred4[ab.x];
    const float4 b = g_pred4[ab.y];
    const float u_A  =  c * a.x + s * a.y;
    const float w_A  = -s * a.x + c * a.y;
    const float thA  = -a.z;
    const float u_B  =  c * b.x + s * b.y;
    const float w_B  = -s * b.x + c * b.y;
    const float thB  = -b.z;
    const float ea_l  = EA * inv_L;
    const float ei_l  = EI * inv_L;
    const float ei_l2 = ei_l * inv_L;
    const float ei_l3 = ei_l2 * inv_L;
    const float dw = w_A - w_B;
    const float f0 = ea_l * (u_A - u_B);
    const float f1 = 12.0f * ei_l3 * dw + 6.0f * ei_l2 * (thA + thB);
    const float f2 = 6.0f * ei_l2 * dw + 4.0f * ei_l * thA + 2.0f * ei_l * thB;
    const float f5 = 6.0f * ei_l2 * dw + 2.0f * ei_l * thA + 4.0f * ei_l * thB;
    const float fAx = c * f0 - s * f1;
    const float fAy = s * f0 + c * f1;
    red_v4(&g_Fint4[ab.x],  fAx,  fAy, -f2, 0.0f);
    red_v4(&g_Fint4[ab.y], -fAx, -fAy, -f5, 0.0f);
}

// Pass 3: masked residual norm, 4 nodes/thread, fused finalize + self-reset.
__global__ void node_kernel(const float4* __restrict__ Fe4,
                            const float*  __restrict__ F_ext,
                            const float4* __restrict__ bcd4,
                            const float4* __restrict__ bcr4,
                            const float*  __restrict__ bcd,
                            const float*  __restrict__ bcr,
                            float* __restrict__ out,
                            int Ngrp, int N) {
    int g = blockIdx.x * blockDim.x + threadIdx.x;
    const int stride = gridDim.x * blockDim.x;

    float lr = 0.0f;
    float lf = 0.0f;
    for (; g < Ngrp; g += stride) {
        const float4 md4 = bcd4[g];
        const float4 mr4 = bcr4[g];
        const float4 e0 = Fe4[3 * g + 0];
        const float4 e1 = Fe4[3 * g + 1];
        const float4 e2 = Fe4[3 * g + 2];
        const int n = 4 * g;
        const float4 i0 = g_Fint4[n + 0];
        const float4 i1 = g_Fint4[n + 1];
        const float4 i2 = g_Fint4[n + 2];
        const float4 i3 = g_Fint4[n + 3];

        // node 0: Fe=(e0.x,e0.y,e0.z)  node1: (e0.w,e1.x,e1.y)
        // node 2: (e1.z,e1.w,e2.x)     node3: (e2.y,e2.z,e2.w)
        {
            const float md = 1.0f - md4.x, mr = 1.0f - mr4.x;
            float R0 = (i0.x - e0.x) * md, R1 = (i0.y - e0.y) * md, R2 = (i0.z - e0.z) * mr;
            float F0 = e0.x * md, F1 = e0.y * md, F2 = e0.z * mr;
            lr += R0*R0 + R1*R1 + R2*R2;  lf += F0*F0 + F1*F1 + F2*F2;
        }
        {
            const float md = 1.0f - md4.y, mr = 1.0f - mr4.y;
            float R0 = (i1.x - e0.w) * md, R1 = (i1.y - e1.x) * md, R2 = (i1.z - e1.y) * mr;
            float F0 = e0.w * md, F1 = e1.x * md, F2 = e1.y * mr;
            lr += R0*R0 + R1*R1 + R2*R2;  lf += F0*F0 + F1*F1 + F2*F2;
        }
        {
            const float md = 1.0f - md4.z, mr = 1.0f - mr4.z;
            float R0 = (i2.x - e1.z) * md, R1 = (i2.y - e1.w) * md, R2 = (i2.z - e2.x) * mr;
            float F0 = e1.z * md, F1 = e1.w * md, F2 = e2.x * mr;
            lr += R0*R0 + R1*R1 + R2*R2;  lf += F0*F0 + F1*F1 + F2*F2;
        }
        {
            const float md = 1.0f - md4.w, mr = 1.0f - mr4.w;
            float R0 = (i3.x - e2.y) * md, R1 = (i3.y - e2.z) * md, R2 = (i3.z - e2.w) * mr;
            float F0 = e2.y * md, F1 = e2.z * md, F2 = e2.w * mr;
            lr += R0*R0 + R1*R1 + R2*R2;  lf += F0*F0 + F1*F1 + F2*F2;
        }
    }
    // scalar tail
    {
        int i = 4 * Ngrp + (blockIdx.x * blockDim.x + threadIdx.x);
        if (i < N) {
            const float md = 1.0f - bcd[i];
            const float mr = 1.0f - bcr[i];
            const float Fe0 = F_ext[3 * i + 0];
            const float Fe1 = F_ext[3 * i + 1];
            const float Fe2 = F_ext[3 * i + 2];
            const float4 Fi = g_Fint4[i];
            const float R0 = (Fi.x - Fe0) * md;
            const float R1 = (Fi.y - Fe1) * md;
            const float R2 = (Fi.z - Fe2) * mr;
            lr += R0*R0 + R1*R1 + R2*R2;
            lf += (Fe0*md)*(Fe0*md) + (Fe1*md)*(Fe1*md) + (Fe2*mr)*(Fe2*mr);
        }
    }

    #pragma unroll
    for (int off = 16; off > 0; off >>= 1) {
        lr += __shfl_down_sync(0xFFFFFFFFu, lr, off);
        lf += __shfl_down_sync(0xFFFFFFFFu, lf, off);
    }

    __shared__ float s_r[32];
    __shared__ float s_f[32];
    const int lane = threadIdx.x & 31;
    const int wid  = threadIdx.x >> 5;
    if (lane == 0) { s_r[wid] = lr; s_f[wid] = lf; }
    __syncthreads();

    __shared__ bool s_last;
    if (wid == 0) {
        const int nwarps = (blockDim.x + 31) >> 5;
        lr = (lane < nwarps) ? s_r[lane] : 0.0f;
        lf = (lane < nwarps) ? s_f[lane] : 0.0f;
        #pragma unroll
        for (int off = 16; off > 0; off >>= 1) {
            lr += __shfl_down_sync(0xFFFFFFFFu, lr, off);
            lf += __shfl_down_sync(0xFFFFFFFFu, lf, off);
        }
        if (lane == 0) {
            atomicAdd(&g_sumR, (double)lr);
            atomicAdd(&g_sumF, (double)lf);
            __threadfence();
            unsigned int t = atomicAdd(&g_ticket, 1u);
            s_last = (t == (unsigned int)(gridDim.x - 1));
        }
    }
    __syncthreads();

    if (threadIdx.x == 0 && s_last) {
        double f = g_sumF;
        if (f < 1e-30) f = 1e-30;
        out[0] = (float)(g_sumR / f);
        g_sumR = 0.0;
        g_sumF = 0.0;
        __threadfence();
        g_ticket = 0u;
    }
}

extern "C" void kernel_launch(void* const* d_in, const int* in_sizes, int n_in,
                              void* d_out, int out_size) {
    const float* pred   = (const float*)d_in[0];
    const float* u_c    = (const float*)d_in[1];
    const float* th_c   = (const float*)d_in[2];
    const float* L      = (const float*)d_in[3];
    const float* pE     = (const float*)d_in[4];
    const float* pA     = (const float*)d_in[5];
    const float* pI     = (const float*)d_in[6];
    const float* dirs   = (const float*)d_in[7];
    const float* F_ext  = (const float*)d_in[8];
    const float* bcd    = (const float*)d_in[9];
    const float* bcr    = (const float*)d_in[10];
    const int*   conn   = (const int*)d_in[11];

    const int N = in_sizes[0] / 3;
    const int E = in_sizes[3];

    float* out = (float*)d_out;

    {
        const int Ngrp = N / 4;
        int threads = 256;
        int blocks = (Ngrp + threads - 1) / threads;
        if (blocks > 2368) blocks = 2368;
        pack_kernel<<<blocks, threads>>>((const float4*)pred, pred, u_c, th_c, Ngrp, N);
    }
    {
        const int Egrp = E / 2;
        int threads = 256;
        int blocks = (Egrp + threads - 1) / threads;
        elem_kernel<<<blocks, threads>>>((const float2*)L, (const float2*)pE,
                                         (const float2*)pA, (const float2*)pI,
                                         (const float2*)dirs, (const int4*)conn, Egrp);
        if (E & 1) {
            elem_tail_kernel<<<1, 32>>>(L, pE, pA, pI, dirs, (const int2*)conn,
                                        2 * Egrp, E);
        }
    }
    {
        const int Ngrp = N / 4;
        int threads = 256;
        int blocks = (Ngrp + threads - 1) / threads;
        if (blocks > 2368) blocks = 2368;
        node_kernel<<<blocks, threads>>>((const float4*)F_ext, F_ext,
                                         (const float4*)bcd, (const float4*)bcr,
                                         bcd, bcr, out, Ngrp, N);
    }
}